// round 3
// baseline (speedup 1.0000x reference)
#include <cuda_runtime.h>
#include <math.h>

#define NPTS   8192
#define KNN    16
#define TPB    256
#define SLICES 4
#define QPB    (TPB/SLICES)      // 64 queries per block
#define TS     2048              // candidates per smem tile
#define TSLICE (TS/SLICES)       // 512 candidates per thread per tile
#define BUF    10
#define MAXB   4

__device__ double g_acc;
__device__ float4 g_ref4[MAXB*NPTS];
__device__ float4 g_pred4[MAXB*NPTS];

__global__ void zero_acc_kernel() { g_acc = 0.0; }

__global__ void prep_kernel(const float* __restrict__ pref,
                            const float* __restrict__ ppred, int total) {
    int i = blockIdx.x * blockDim.x + threadIdx.x;
    if (i >= total) return;
    float x = pref[3*i], y = pref[3*i+1], z = pref[3*i+2];
    g_ref4[i] = make_float4(x, y, z, 0.5f*(x*x + y*y + z*z));
    g_pred4[i] = make_float4(ppred[3*i], ppred[3*i+1], ppred[3*i+2], 0.0f);
}

__global__ void finalize_kernel(float* out, float inv_total) {
    out[0] = (float)(g_acc) * inv_total;
}

__global__ __launch_bounds__(TPB)
void knn_loss_kernel() {
    __shared__ float4 tile[TS];          // 32KB; reused for the merge phase
    __shared__ float  bufv[BUF][TPB];    // 10KB
    __shared__ int    bufi[BUF][TPB];    // 10KB
    __shared__ float  warpsum[TPB/32];

    const int t     = threadIdx.x;
    const int slice = t & (SLICES - 1);
    const int qloc  = t >> 2;
    const int blocks_per_batch = NPTS / QPB;                 // 128
    const int b    = blockIdx.x / blocks_per_batch;
    const int i    = (blockIdx.x % blocks_per_batch) * QPB + qloc;
    const int base = b * NPTS;

    const float4 q = g_ref4[base + i];
    const float xi = q.x, yi = q.y, zi = q.z;

    // top-KNN scores, sorted ascending in registers (static indexing only)
    float val[KNN];
    int   idx[KNN];
#pragma unroll
    for (int k = 0; k < KNN; k++) { val[k] = __int_as_float(0x7F800000); idx[k] = 0; }
    float cmax = __int_as_float(0x7F800000);
    int cnt = 0;

    // branchless sorted insert; caller guarantees v < cmax
    auto insert = [&](float v, int id) {
        float cv = v; int ci = id;
#pragma unroll
        for (int k = 0; k < KNN; k++) {
            bool sw = cv < val[k];
            float nv = sw ? cv : val[k];
            int   ni = sw ? ci : idx[k];
            float tv = sw ? val[k] : cv;
            int   ti = sw ? idx[k] : ci;
            val[k] = nv; idx[k] = ni;
            cv = tv; ci = ti;
        }
        cmax = val[KNN-1];
    };

    auto flush = [&]() {
        for (int u = 0; u < cnt; u++) {
            float v = bufv[u][t];
            if (v < cmax) insert(v, bufi[u][t]);
        }
        cnt = 0;
    };

    for (int t0 = 0; t0 < NPTS; t0 += TS) {
        __syncthreads();
        for (int m = t; m < TS; m += TPB)
            tile[m] = g_ref4[base + t0 + m];
        __syncthreads();

        const int jbase = slice * TSLICE;
        for (int jj0 = 0; jj0 < TSLICE; jj0 += 8) {
#pragma unroll
            for (int u = 0; u < 8; u++) {
                int j = jbase + jj0 + u;
                float4 c = tile[j];
                // score = 0.5|p|^2 - p.q  ==  (d2 - |q|^2)/2 : same ordering as d2
                float sc = fmaf(-c.x, xi, fmaf(-c.y, yi, fmaf(-c.z, zi, c.w)));
                if (sc < cmax) {
                    int gj = t0 + j;
                    if (gj != i) { bufv[cnt][t] = sc; bufi[cnt][t] = gj; cnt++; }
                }
            }
            // warp-collective flush: amortizes expensive rescans across lanes
            if (__ballot_sync(0xFFFFFFFFu, cnt >= 3)) flush();
        }
    }
    flush();

    // ---- merge the 4 slices of each query (threads t..t+3 share query) ----
    __syncthreads();
    float* mv = (float*)tile;                                   // [TPB][KNN]
    int*   mi = (int*)((char*)tile + TPB * KNN * sizeof(float));
#pragma unroll
    for (int k = 0; k < KNN; k++) { mv[t*KNN + k] = val[k]; mi[t*KNN + k] = idx[k]; }
    __syncthreads();

    float s = 0.0f;
    if (slice == 0) {
        for (int ss = 1; ss < SLICES; ss++) {
            for (int k = 0; k < KNN; k++) {
                float v = mv[(t + ss)*KNN + k];
                if (v < cmax) insert(v, mi[(t + ss)*KNN + k]);
            }
        }
        // epilogue: exact edge lengths for the selected 16 neighbors
        const float4 qp = g_pred4[base + i];
#pragma unroll
        for (int k = 0; k < KNN; k++) {
            int j = idx[k];
            float4 r = g_ref4[base + j];
            float4 p = g_pred4[base + j];
            float dx = r.x - xi, dy = r.y - yi, dz = r.z - zi;
            float dr = sqrtf(fmaf(dx, dx, fmaf(dy, dy, dz*dz)));
            float ex = p.x - qp.x, ey = p.y - qp.y, ez = p.z - qp.z;
            float dp = sqrtf(fmaf(ex, ex, fmaf(ey, ey, ez*ez)));
            s += fabsf(dr - dp);
        }
    }

#pragma unroll
    for (int o = 16; o > 0; o >>= 1)
        s += __shfl_down_sync(0xFFFFFFFFu, s, o);
    if ((t & 31) == 0) warpsum[t >> 5] = s;
    __syncthreads();
    if (t == 0) {
        float tt = 0.0f;
#pragma unroll
        for (int w = 0; w < TPB/32; w++) tt += warpsum[w];
        atomicAdd(&g_acc, (double)tt);
    }
}

extern "C" void kernel_launch(void* const* d_in, const int* in_sizes, int n_in,
                              void* d_out, int out_size) {
    const float* points_ref = (const float*)d_in[0];
    const float* points     = (const float*)d_in[1];
    float* out = (float*)d_out;

    const int B = in_sizes[0] / (NPTS * 3);                  // 4
    const int total_pts = B * NPTS;
    const float inv_total = 1.0f / (float)(B * NPTS * KNN);
    const int nblocks = B * (NPTS / QPB);                    // 512

    zero_acc_kernel<<<1, 1>>>();
    prep_kernel<<<(total_pts + TPB - 1) / TPB, TPB>>>(points_ref, points, total_pts);
    knn_loss_kernel<<<nblocks, TPB>>>();
    finalize_kernel<<<1, 1>>>(out, inv_total);
}

// round 4
// speedup vs baseline: 1.6539x; 1.6539x over previous
#include <cuda_runtime.h>
#include <math.h>

#define NPTS   8192
#define KNN    16
#define TPB    256
#define BPB    37            // blocks per batch  (148 total blocks, all SMs)
#define NBLK   (4*BPB)
#define IDXBITS 13
#define IDXMASK ((1u<<IDXBITS)-1u)

__device__ double g_acc;
__device__ unsigned g_done;
__device__ float4 g_ref4[4*NPTS];    // (x, y, z, |p|^2/2)
__device__ float4 g_pred4[4*NPTS];

__global__ void prep_kernel(const float* __restrict__ pref,
                            const float* __restrict__ ppred, int total) {
    int i = blockIdx.x * blockDim.x + threadIdx.x;
    if (i == 0) { g_acc = 0.0; g_done = 0u; }
    if (i >= total) return;
    float x = pref[3*i], y = pref[3*i+1], z = pref[3*i+2];
    g_ref4[i]  = make_float4(x, y, z, 0.5f*(x*x + y*y + z*z));
    g_pred4[i] = make_float4(ppred[3*i], ppred[3*i+1], ppred[3*i+2], 0.0f);
}

__global__ __launch_bounds__(TPB)
void knn_loss_kernel(float* __restrict__ out, float inv_total) {
    extern __shared__ float4 tile[];          // NPTS float4 = 128KB
    __shared__ float warpsum[TPB/32];

    const int t  = threadIdx.x;
    const int b  = blockIdx.x / BPB;          // batch
    const int r  = blockIdx.x % BPB;
    const int q0 = (NPTS *  r)      / BPB;
    const int q1 = (NPTS * (r + 1)) / BPB;    // q1-q0 <= 222 <= TPB
    const int base = b * NPTS;
    const int i  = q0 + t;                    // batch-local query id
    const bool active = (i < q1);

    // load entire batch tile (all threads help)
    for (int m = t; m < NPTS; m += TPB)
        tile[m] = g_ref4[base + m];
    __syncthreads();

    float xi = 0.f, yi = 0.f, zi = 0.f, hq = 0.f;
    if (active) {
        float4 q = tile[i];
        xi = q.x; yi = q.y; zi = q.z; hq = q.w;   // hq = |q|^2/2
    }

    // sorted ascending top-16 of packed (score | index)
    float val[KNN];
#pragma unroll
    for (int k = 0; k < KNN; k++) val[k] = __int_as_float(0x7F000000);
    float cmax = active ? __int_as_float(0x7F000000) : -1.0f;  // inactive: never accept

#pragma unroll 8
    for (int j = 0; j < NPTS; j++) {
        float4 c = tile[j];
        // sc = d2/2 = (|p|^2/2 + |q|^2/2) - p.q   (>= 0 up to rounding)
        float acc = c.w + hq;
        float sc = fmaf(-c.x, xi, fmaf(-c.y, yi, fmaf(-c.z, zi, acc)));
        if (sc < cmax && j != i) {
            // pack index into mantissa LSBs; float ordering preserved
            float cv = __int_as_float((__float_as_int(sc) & ~(int)IDXMASK) | j);
#pragma unroll
            for (int k = 0; k < KNN; k++) {
                float lo = fminf(cv, val[k]);
                float hi = fmaxf(cv, val[k]);
                val[k] = lo; cv = hi;
            }
            cmax = val[KNN-1];
        }
    }

    // epilogue: exact edge lengths for the selected 16 neighbors
    float s = 0.0f;
    if (active) {
        const float4 qp = g_pred4[base + i];
#pragma unroll
        for (int k = 0; k < KNN; k++) {
            int j = __float_as_int(val[k]) & (int)IDXMASK;
            float4 rr = tile[j];
            float4 pp = g_pred4[base + j];
            float dx = rr.x - xi, dy = rr.y - yi, dz = rr.z - zi;
            float dr = sqrtf(fmaf(dx, dx, fmaf(dy, dy, dz*dz)));
            float ex = pp.x - qp.x, ey = pp.y - qp.y, ez = pp.z - qp.z;
            float dp = sqrtf(fmaf(ex, ex, fmaf(ey, ey, ez*ez)));
            s += fabsf(dr - dp);
        }
    }

#pragma unroll
    for (int o = 16; o > 0; o >>= 1)
        s += __shfl_down_sync(0xFFFFFFFFu, s, o);
    if ((t & 31) == 0) warpsum[t >> 5] = s;
    __syncthreads();

    if (t == 0) {
        float tt = 0.0f;
#pragma unroll
        for (int w = 0; w < TPB/32; w++) tt += warpsum[w];
        atomicAdd(&g_acc, (double)tt);
        __threadfence();
        unsigned old = atomicAdd(&g_done, 1u);
        if (old == NBLK - 1) {
            double total = atomicAdd(&g_acc, 0.0);   // safe read-after-fence
            out[0] = (float)total * inv_total;
        }
    }
}

extern "C" void kernel_launch(void* const* d_in, const int* in_sizes, int n_in,
                              void* d_out, int out_size) {
    const float* points_ref = (const float*)d_in[0];
    const float* points     = (const float*)d_in[1];
    float* out = (float*)d_out;

    const int B = in_sizes[0] / (NPTS * 3);               // 4
    const int total_pts = B * NPTS;
    const float inv_total = 1.0f / (float)(B * NPTS * KNN);

    static int smem_set = 0;
    if (!smem_set) {
        cudaFuncSetAttribute(knn_loss_kernel,
                             cudaFuncAttributeMaxDynamicSharedMemorySize,
                             NPTS * (int)sizeof(float4));
        smem_set = 1;
    }

    prep_kernel<<<(total_pts + TPB - 1) / TPB, TPB>>>(points_ref, points, total_pts);
    knn_loss_kernel<<<NBLK, TPB, NPTS * sizeof(float4)>>>(out, inv_total);
}

// round 5
// speedup vs baseline: 1.8664x; 1.1285x over previous
#include <cuda_runtime.h>
#include <math.h>

#define NPTS   8192
#define KNN    16
#define KL     17            // 16 + self slot (self edge contributes 0)
#define TPB    256
#define BPB    37            // blocks per batch -> 148 blocks total
#define NBLK   (4*BPB)
#define IDXMASK 8191         // 13 bits

__device__ double g_acc;
__device__ unsigned g_done;
__device__ float4 g_ref4[4*NPTS];    // (x, y, z, |p|^2/2)
__device__ float4 g_pred4[4*NPTS];

__global__ void prep_kernel(const float* __restrict__ pref,
                            const float* __restrict__ ppred, int total) {
    int i = blockIdx.x * blockDim.x + threadIdx.x;
    if (i == 0) { g_acc = 0.0; g_done = 0u; }
    if (i >= total) return;
    float x = pref[3*i], y = pref[3*i+1], z = pref[3*i+2];
    g_ref4[i]  = make_float4(x, y, z, 0.5f*(x*x + y*y + z*z));
    g_pred4[i] = make_float4(ppred[3*i], ppred[3*i+1], ppred[3*i+2], 0.0f);
}

__global__ __launch_bounds__(TPB)
void knn_loss_kernel(float* __restrict__ out, float inv_total) {
    extern __shared__ float4 tile[];          // NPTS float4 = 128KB
    __shared__ float warpsum[TPB/32];

    const int t  = threadIdx.x;
    const int b  = blockIdx.x / BPB;
    const int r  = blockIdx.x % BPB;
    const int q0 = (NPTS *  r)      / BPB;
    const int q1 = (NPTS * (r + 1)) / BPB;    // 221..222 queries per block
    const int base = b * NPTS;
    const int i  = q0 + t;
    const bool active = (i < q1);

    for (int m = t; m < NPTS; m += TPB)
        tile[m] = g_ref4[base + m];
    __syncthreads();

    float s = 0.0f;
    if (active) {
        const float4 q = tile[i];
        const float xi = q.x, yi = q.y, zi = q.z, hq = q.w;

        // sorted ascending top-17 of packed (score | index); self included
        float val[KL];
#pragma unroll
        for (int k = 0; k < KL; k++) val[k] = __int_as_float(0x7F000000);
        float cmax = __int_as_float(0x7F000000);

#pragma unroll 1
        for (int j0 = 0; j0 < NPTS; j0 += 8) {
            float sc[8];
#pragma unroll
            for (int u = 0; u < 8; u++) {
                float4 c = tile[j0 + u];
                sc[u] = fmaf(-c.x, xi, fmaf(-c.y, yi, fmaf(-c.z, zi, c.w + hq)));
            }
            // min-tree over the 8 scores -> one branch for the whole group
            float m01 = fminf(sc[0], sc[1]), m23 = fminf(sc[2], sc[3]);
            float m45 = fminf(sc[4], sc[5]), m67 = fminf(sc[6], sc[7]);
            float mall = fminf(fminf(m01, m23), fminf(m45, m67));
            if (mall < cmax) {
#pragma unroll
                for (int u = 0; u < 8; u++) {
                    if (sc[u] < cmax) {
                        float cv = __int_as_float(
                            (__float_as_int(sc[u]) & ~IDXMASK) | (j0 + u));
#pragma unroll
                        for (int k = 0; k < KL; k++) {
                            float lo = fminf(cv, val[k]);
                            float hi = fmaxf(cv, val[k]);
                            val[k] = lo; cv = hi;
                        }
                        cmax = val[KL-1];
                    }
                }
            }
        }

        // epilogue: exact edge lengths; the self entry contributes |0-0| = 0
        const float4 qp = g_pred4[base + i];
#pragma unroll
        for (int k = 0; k < KL; k++) {
            int j = __float_as_int(val[k]) & IDXMASK;
            float4 rr = tile[j];
            float4 pp = g_pred4[base + j];
            float dx = rr.x - xi, dy = rr.y - yi, dz = rr.z - zi;
            float dr = sqrtf(fmaf(dx, dx, fmaf(dy, dy, dz*dz)));
            float ex = pp.x - qp.x, ey = pp.y - qp.y, ez = pp.z - qp.z;
            float dp = sqrtf(fmaf(ex, ex, fmaf(ey, ey, ez*ez)));
            s += fabsf(dr - dp);
        }
    }

#pragma unroll
    for (int o = 16; o > 0; o >>= 1)
        s += __shfl_down_sync(0xFFFFFFFFu, s, o);
    if ((t & 31) == 0) warpsum[t >> 5] = s;
    __syncthreads();

    if (t == 0) {
        float tt = 0.0f;
#pragma unroll
        for (int w = 0; w < TPB/32; w++) tt += warpsum[w];
        atomicAdd(&g_acc, (double)tt);
        __threadfence();
        unsigned old = atomicAdd(&g_done, 1u);
        if (old == NBLK - 1) {
            double total = atomicAdd(&g_acc, 0.0);
            out[0] = (float)total * inv_total;
        }
    }
}

extern "C" void kernel_launch(void* const* d_in, const int* in_sizes, int n_in,
                              void* d_out, int out_size) {
    const float* points_ref = (const float*)d_in[0];
    const float* points     = (const float*)d_in[1];
    float* out = (float*)d_out;

    const int B = in_sizes[0] / (NPTS * 3);               // 4
    const int total_pts = B * NPTS;
    const float inv_total = 1.0f / (float)(B * NPTS * KNN);

    static int smem_set = 0;
    if (!smem_set) {
        cudaFuncSetAttribute(knn_loss_kernel,
                             cudaFuncAttributeMaxDynamicSharedMemorySize,
                             NPTS * (int)sizeof(float4));
        smem_set = 1;
    }

    prep_kernel<<<(total_pts + TPB - 1) / TPB, TPB>>>(points_ref, points, total_pts);
    knn_loss_kernel<<<NBLK, TPB, NPTS * sizeof(float4)>>>(out, inv_total);
}